// round 16
// baseline (speedup 1.0000x reference)
#include <cuda_runtime.h>
#include <cstdint>

#define BATCH 8
#define SEQ   1024
#define DIM   768
#define EPS_F 1e-7f

// Both GEMMs: 128x128 block, 8 warps 64x32, BK=32, swizzled 32-word rows.
#define STAGES   3
#define STAGE_B  32768                      // A-op 16KB + B-op 16KB
#define SMEM_B   (STAGES * STAGE_B)         // 98304
#define PV_SMEM  (SMEM_B + 512)             // + den[128]
#define PADT 132                            // qk transpose-stage stride

// k-permutation within 8-groups: pos(k) = (k&3)*2 + (k>>2)
__device__ __forceinline__ int pcol(int c) {
    return (c & ~7) | (((c & 3) << 1) + ((c >> 2) & 1));
}

// Scratch (allocation-free rule: __device__ globals)
__device__ float g_Atf[(size_t)BATCH * SEQ * DIM];  // tf32, [S][D], D-permuted
__device__ float g_AT [(size_t)BATCH * DIM * SEQ];  // tf32, [D][S], S-permuted
__device__ float g_E[(size_t)BATCH * SEQ * SEQ];    // tf32 exp scores, col-permuted
__device__ float g_partial[(size_t)BATCH * SEQ * 32];

__device__ __forceinline__ uint32_t smem_u32(const void* p) {
    uint32_t a;
    asm("{ .reg .u64 t; cvta.to.shared.u64 t, %1; cvt.u32.u64 %0, t; }" : "=r"(a) : "l"(p));
    return a;
}
__device__ __forceinline__ uint32_t f2tf(float x) {
    uint32_t u; asm("cvt.rna.tf32.f32 %0, %1;" : "=r"(u) : "f"(x)); return u;
}
__device__ __forceinline__ float f2tff(float x) {
    return __uint_as_float(f2tf(x));
}
__device__ __forceinline__ void mma_tf32(float c[4],
                                         uint32_t a0, uint32_t a1, uint32_t a2, uint32_t a3,
                                         uint32_t b0, uint32_t b1) {
    asm("mma.sync.aligned.m16n8k8.row.col.f32.tf32.tf32.f32 "
        "{%0,%1,%2,%3}, {%4,%5,%6,%7}, {%8,%9}, {%0,%1,%2,%3};"
        : "+f"(c[0]), "+f"(c[1]), "+f"(c[2]), "+f"(c[3])
        : "r"(a0), "r"(a1), "r"(a2), "r"(a3), "r"(b0), "r"(b1));
}
__device__ __forceinline__ void cp16(uint32_t saddr, const void* g) {
    asm volatile("cp.async.cg.shared.global [%0], [%1], 16;" :: "r"(saddr), "l"(g));
}
#define CP_COMMIT() asm volatile("cp.async.commit_group;" ::: "memory")
#define CP_WAIT1()  asm volatile("cp.async.wait_group 1;" ::: "memory")

// swizzled fragment byte-offset inside a [rows][32 words] tile
#define SWOFF(row, ks) \
    ((uint32_t)(row) * 128u + (uint32_t)((((2*(ks)) + cb) ^ swz) << 4) + w8)

// ---------------------------------------------------------------------------
// Compute core with one-step fragment software pipelining and cp.async issue
// interleaved after each ks-step (ISS(ks): 2 cp16s; smooths MIO bursts).
// ---------------------------------------------------------------------------
#define COMPUTE_PIPE_I(AsBuf, BsBuf, ISS) do {                                \
    uint2 bq[4], nbq[4];                                                      \
    _Pragma("unroll")                                                         \
    for (int nt = 0; nt < 4; nt++)                                            \
        bq[nt] = *(const uint2*)((BsBuf) + SWOFF(nBase + nt * 8 + qid, 0));   \
    _Pragma("unroll")                                                         \
    for (int ks = 0; ks < 4; ks++) {                                          \
        if (ks < 3) {                                                         \
            _Pragma("unroll")                                                 \
            for (int nt = 0; nt < 4; nt++)                                    \
                nbq[nt] = *(const uint2*)((BsBuf) +                           \
                    SWOFF(nBase + nt * 8 + qid, ks + 1));                     \
        }                                                                     \
        uint2 aL = *(const uint2*)((AsBuf) + SWOFF(mBase + qid, ks));         \
        uint2 aH = *(const uint2*)((AsBuf) + SWOFF(mBase + qid + 8, ks));     \
        _Pragma("unroll")                                                     \
        for (int mt = 0; mt < 4; mt++) {                                      \
            uint2 naL, naH;                                                   \
            if (mt < 3) {                                                     \
                naL = *(const uint2*)((AsBuf) +                               \
                    SWOFF(mBase + (mt + 1) * 16 + qid, ks));                  \
                naH = *(const uint2*)((AsBuf) +                               \
                    SWOFF(mBase + (mt + 1) * 16 + qid + 8, ks));              \
            }                                                                 \
            _Pragma("unroll")                                                 \
            for (int nt = 0; nt < 4; nt++)                                    \
                mma_tf32(acc[mt][nt], aL.x, aH.x, aL.y, aH.y,                 \
                         bq[nt].x, bq[nt].y);                                 \
            if (mt < 3) { aL = naL; aH = naH; }                               \
        }                                                                     \
        ISS(ks);                                                              \
        if (ks < 3) {                                                         \
            _Pragma("unroll")                                                 \
            for (int nt = 0; nt < 4; nt++) bq[nt] = nbq[nt];                  \
        }                                                                     \
    }                                                                         \
} while (0)

// ---------------------------------------------------------------------------
// Kernel 0: fused tf32 round + dual layout.  Permuted 8-group writes are
// gathered so both outputs use STG.128 (2 float4s per 8-group).
// ---------------------------------------------------------------------------
__global__ void __launch_bounds__(256) cvt_trans_kernel(const float* __restrict__ A)
{
    __shared__ float tile[32][33];
    const int b  = blockIdx.z;
    const int d0 = blockIdx.x * 32;
    const int s0 = blockIdx.y * 32;
    const int t  = threadIdx.x;
    const int tx = t & 31;
    const int ty = t >> 5;
    const float* Ab = A + (size_t)b * SEQ * DIM;

    #pragma unroll
    for (int j = 0; j < 4; j++)
        tile[ty + 8 * j][tx] = Ab[(size_t)(s0 + ty + 8 * j) * DIM + d0 + tx];
    __syncthreads();

    // 256 threads: t<128 -> Fb tasks, t>=128 -> Tb tasks.
    // Task = (row 0..31, 8-group 0..3): gather 8 values in permuted order,
    // emit 2 float4s.  pos p holds source index (p>>1) + (p&1)*4.
    const int row = (t >> 2) & 31;
    const int grp = t & 3;
    if (t < 128) {
        const float* src = &tile[row][grp * 8];
        float4 v0 = make_float4(f2tff(src[0]), f2tff(src[4]),
                                f2tff(src[1]), f2tff(src[5]));
        float4 v1 = make_float4(f2tff(src[2]), f2tff(src[6]),
                                f2tff(src[3]), f2tff(src[7]));
        float* dst = g_Atf + (size_t)b * SEQ * DIM
                   + (size_t)(s0 + row) * DIM + d0 + grp * 8;
        *(float4*)dst       = v0;
        *(float4*)(dst + 4) = v1;
    } else {
        // column gather: value at out pos p = tile[grp*8 + invp(p)][row]
        const int sbase = grp * 8;
        float4 v0 = make_float4(f2tff(tile[sbase + 0][row]), f2tff(tile[sbase + 4][row]),
                                f2tff(tile[sbase + 1][row]), f2tff(tile[sbase + 5][row]));
        float4 v1 = make_float4(f2tff(tile[sbase + 2][row]), f2tff(tile[sbase + 6][row]),
                                f2tff(tile[sbase + 3][row]), f2tff(tile[sbase + 7][row]));
        float* dst = g_AT + (size_t)b * DIM * SEQ
                   + (size_t)(d0 + row) * SEQ + s0 + grp * 8;
        *(float4*)dst       = v0;
        *(float4*)(dst + 4) = v1;
    }
}

// ---------------------------------------------------------------------------
// Kernel 1: E = exp(A A^T) * masks, triangle-linearized grid (36 tiles/batch).
// Order: wait_group 1 -> sync -> compute(it) with interleaved issue(it+2).
// ---------------------------------------------------------------------------
__global__ void __launch_bounds__(256, 2) qk_exp_mma(const int* __restrict__ mask)
{
    extern __shared__ float dsm[];

    int by = 0, rem = blockIdx.x;
    while (rem >= 8 - by) { rem -= 8 - by; by++; }
    const int bx = by + rem;
    const bool offdiag = (bx > by);

    const int b       = blockIdx.z;
    const int rowBase = by * 128;
    const int colBase = bx * 128;
    const float* Ab = g_Atf + (size_t)b * SEQ * DIM;
    const int bS = b * SEQ;

    const int tid  = threadIdx.x;
    const int wid  = tid >> 5;
    const int lane = tid & 31;
    const int qid  = lane >> 2;
    const int tq   = lane & 3;
    const int mBase = (wid >> 2) * 64;
    const int nBase = (wid & 3) * 32;
    const int wr   = wid >> 2;
    const int wc   = wid & 3;

    const uint32_t cb  = (uint32_t)(tq >> 1);
    const uint32_t w8  = (uint32_t)((tq & 1) * 8);
    const uint32_t swz = (uint32_t)((qid & 3) << 1);

    const uint32_t sb = smem_u32(dsm);

    const float* gA[4]; const float* gB[4]; uint32_t dstT[4];
    #pragma unroll
    for (int l = 0; l < 4; l++) {
        int idx = tid + l * 256;
        int r   = idx >> 3;
        int c   = idx & 7;
        dstT[l] = (uint32_t)(r * 128 + ((c ^ ((r & 3) << 1)) << 4));
        gA[l]   = Ab + (size_t)(rowBase + r) * DIM + c * 4;
        gB[l]   = Ab + (size_t)(colBase + r) * DIM + c * 4;
    }

    float acc[4][4][4];
    #pragma unroll
    for (int i = 0; i < 4; i++)
        #pragma unroll
        for (int j = 0; j < 4; j++)
            #pragma unroll
            for (int k = 0; k < 4; k++) acc[i][j][k] = 0.f;

    const int NT = DIM / 32;   // 24

    #pragma unroll
    for (int s = 0; s < STAGES - 1; s++) {
        const uint32_t so = s * STAGE_B;
        const int k0 = s * 32;
        #pragma unroll
        for (int l = 0; l < 4; l++) {
            cp16(sb + so + dstT[l], gA[l] + k0);
            cp16(sb + so + 16384 + dstT[l], gB[l] + k0);
        }
        CP_COMMIT();
    }

#define QK_ISS(j) do { if (tn < NT) {                                   \
        cp16(sb + so + dstT[j], gA[j] + k0);                            \
        cp16(sb + so + 16384 + dstT[j], gB[j] + k0); } } while (0)

    for (int it = 0; it < NT; it++) {
        CP_WAIT1();                 // per-thread: tile it complete
        __syncthreads();            // collective publish / free
        const int tn = it + 2;
        const uint32_t so = (tn % STAGES) * STAGE_B;
        const int k0 = tn * 32;
        const char* As = (const char*)dsm + (it % STAGES) * STAGE_B;
        const char* Bs = As + 16384;
        COMPUTE_PIPE_I(As, Bs, QK_ISS);
        CP_COMMIT();
    }
#undef QK_ISS

    __syncthreads();
    float* stage = dsm;

    float cs[4][2];
    #pragma unroll
    for (int nt = 0; nt < 4; nt++) { cs[nt][0] = 0.f; cs[nt][1] = 0.f; }

    #pragma unroll
    for (int mt = 0; mt < 4; mt++) {
        const int rrl = mBase + mt * 16 + qid;
        const int rr  = rowBase + rrl;
        const int prr = pcol(rrl);
        const float mr0 = (float)mask[bS + rr];
        const float mr1 = (float)mask[bS + rr + 8];
        float s0 = 0.f, s1 = 0.f;
        #pragma unroll
        for (int nt = 0; nt < 4; nt++) {
            const int ccl = nBase + nt * 8 + tq * 2;
            const int cc  = colBase + ccl;
            const float mc0 = (float)mask[bS + cc];
            const float mc1 = (float)mask[bS + cc + 1];
            float e00 = f2tff(__expf(acc[mt][nt][0]) * mr0 * mc0);
            float e01 = f2tff(__expf(acc[mt][nt][1]) * mr0 * mc1);
            float e10 = f2tff(__expf(acc[mt][nt][2]) * mr1 * mc0);
            float e11 = f2tff(__expf(acc[mt][nt][3]) * mr1 * mc1);
            s0 += e00 + e01;
            s1 += e10 + e11;
            const int pc = colBase + pcol(ccl);
            float* er0 = &g_E[((size_t)bS + rr) * SEQ + pc];
            float* er1 = &g_E[((size_t)bS + rr + 8) * SEQ + pc];
            er0[0] = e00; er0[2] = e01;
            er1[0] = e10; er1[2] = e11;
            if (offdiag) {
                cs[nt][0] += e00 + e10;
                cs[nt][1] += e01 + e11;
                stage[ccl * PADT + prr]           = e00;
                stage[(ccl + 1) * PADT + prr]     = e01;
                stage[ccl * PADT + prr + 8]       = e10;
                stage[(ccl + 1) * PADT + prr + 8] = e11;
            }
        }
        s0 += __shfl_xor_sync(0xffffffffu, s0, 1);
        s0 += __shfl_xor_sync(0xffffffffu, s0, 2);
        s1 += __shfl_xor_sync(0xffffffffu, s1, 1);
        s1 += __shfl_xor_sync(0xffffffffu, s1, 2);
        if (tq == 0) {
            g_partial[((size_t)bS + rr) * 32 + bx * 4 + wc]     = s0;
            g_partial[((size_t)bS + rr + 8) * 32 + bx * 4 + wc] = s1;
        }
    }

    if (offdiag) {
        #pragma unroll
        for (int nt = 0; nt < 4; nt++) {
            #pragma unroll
            for (int h = 0; h < 2; h++) {
                float v = cs[nt][h];
                v += __shfl_xor_sync(0xffffffffu, v, 4);
                v += __shfl_xor_sync(0xffffffffu, v, 8);
                v += __shfl_xor_sync(0xffffffffu, v, 16);
                cs[nt][h] = v;
            }
        }
        if (qid == 0) {
            #pragma unroll
            for (int nt = 0; nt < 4; nt++) {
                const int cc = colBase + nBase + nt * 8 + tq * 2;
                g_partial[((size_t)bS + cc) * 32 + by * 4 + wr]         = cs[nt][0];
                g_partial[((size_t)bS + cc + 1) * 32 + by * 4 + wr]     = cs[nt][1];
                g_partial[((size_t)bS + cc) * 32 + by * 4 + 2 + wr]     = 0.f;
                g_partial[((size_t)bS + cc + 1) * 32 + by * 4 + 2 + wr] = 0.f;
            }
        }
        __syncthreads();
        #pragma unroll
        for (int l = 0; l < 16; l++) {
            int idx = tid + l * 256;
            int c   = idx >> 5;
            int r4  = (idx & 31) << 2;
            float4 v = *(float4*)&stage[c * PADT + r4];
            *(float4*)&g_E[((size_t)bS + colBase + c) * SEQ + rowBase + r4] = v;
        }
    }
}

// ---------------------------------------------------------------------------
// Kernel 2: out = (E @ A) / den.  Denominators folded into prologue (SMEM).
// ---------------------------------------------------------------------------
__global__ void __launch_bounds__(256, 2) pv_mma(float* __restrict__ out)
{
    extern __shared__ float dsm[];
    float* den_s = dsm + SMEM_B / 4;

    const int b       = blockIdx.z;
    const int rowBase = blockIdx.y * 128;
    const int colBase = blockIdx.x * 128;
    const float* ATb = g_AT + (size_t)b * DIM * SEQ;
    const float* Eb  = g_E  + (size_t)b * SEQ * SEQ;
    const int bS = b * SEQ;

    const int tid  = threadIdx.x;
    const int wid  = tid >> 5;
    const int lane = tid & 31;
    const int qid  = lane >> 2;
    const int tq   = lane & 3;
    const int mBase = (wid >> 2) * 64;
    const int nBase = (wid & 3) * 32;

    const uint32_t cb  = (uint32_t)(tq >> 1);
    const uint32_t w8  = (uint32_t)((tq & 1) * 8);
    const uint32_t swz = (uint32_t)((qid & 3) << 1);

    const uint32_t sb = smem_u32(dsm);

    const float* gE[4]; const float* gV[4]; uint32_t dstT[4];
    #pragma unroll
    for (int l = 0; l < 4; l++) {
        int idx = tid + l * 256;
        int r   = idx >> 3;
        int c   = idx & 7;
        dstT[l] = (uint32_t)(r * 128 + ((c ^ ((r & 3) << 1)) << 4));
        gE[l]   = Eb  + (size_t)(rowBase + r) * SEQ + c * 4;
        gV[l]   = ATb + (size_t)(colBase + r) * SEQ + c * 4;
    }

    #pragma unroll
    for (int s = 0; s < STAGES - 1; s++) {
        const uint32_t so = s * STAGE_B;
        const int k0 = s * 32;
        #pragma unroll
        for (int l = 0; l < 4; l++) {
            cp16(sb + so + dstT[l], gE[l] + k0);
            cp16(sb + so + 16384 + dstT[l], gV[l] + k0);
        }
        CP_COMMIT();
    }

    // denominator fold: 2 threads/row; published by first mainloop sync
    {
        const int row = tid >> 1;
        const int h   = tid & 1;
        const float* p = g_partial + ((size_t)bS + rowBase + row) * 32 + h * 16;
        float s = 0.f;
        #pragma unroll
        for (int j = 0; j < 16; j++) s += p[j];
        s += __shfl_xor_sync(0xffffffffu, s, 1);
        if (h == 0) den_s[row] = s + EPS_F;
    }

    float acc[4][4][4];
    #pragma unroll
    for (int i = 0; i < 4; i++)
        #pragma unroll
        for (int j = 0; j < 4; j++)
            #pragma unroll
            for (int k = 0; k < 4; k++) acc[i][j][k] = 0.f;

    const int NT = SEQ / 32;   // 32

#define PV_ISS(j) do { if (tn < NT) {                                   \
        cp16(sb + so + dstT[j], gE[j] + k0);                            \
        cp16(sb + so + 16384 + dstT[j], gV[j] + k0); } } while (0)

    for (int it = 0; it < NT; it++) {
        CP_WAIT1();
        __syncthreads();
        const int tn = it + 2;
        const uint32_t so = (tn % STAGES) * STAGE_B;
        const int k0 = tn * 32;
        const char* Es = (const char*)dsm + (it % STAGES) * STAGE_B;
        const char* Vs = Es + 16384;
        COMPUTE_PIPE_I(Es, Vs, PV_ISS);
        CP_COMMIT();
    }
#undef PV_ISS

    // Epilogue: scale by 1/den (from SMEM), coalesced float2 stores.
    #pragma unroll
    for (int mt = 0; mt < 4; mt++) {
        const int rl = mBase + mt * 16 + qid;
        const int rr = rowBase + rl;
        const float inv0 = 1.0f / den_s[rl];
        const float inv1 = 1.0f / den_s[rl + 8];
        #pragma unroll
        for (int nt = 0; nt < 4; nt++) {
            const int cc = colBase + nBase + nt * 8 + tq * 2;
            *(float2*)&out[((size_t)bS + rr) * DIM + cc] =
                make_float2(acc[mt][nt][0] * inv0, acc[mt][nt][1] * inv0);
            *(float2*)&out[((size_t)bS + rr + 8) * DIM + cc] =
                make_float2(acc[mt][nt][2] * inv1, acc[mt][nt][3] * inv1);
        }
    }
}

// ---------------------------------------------------------------------------
extern "C" void kernel_launch(void* const* d_in, const int* in_sizes, int n_in,
                              void* d_out, int out_size)
{
    const float* A    = (const float*)d_in[0];
    const int*   mask = (const int*)d_in[1];
    float*       out  = (float*)d_out;

    cudaFuncSetAttribute(qk_exp_mma, cudaFuncAttributeMaxDynamicSharedMemorySize, SMEM_B);
    cudaFuncSetAttribute(pv_mma,     cudaFuncAttributeMaxDynamicSharedMemorySize, PV_SMEM);

    dim3 gc(DIM / 32, SEQ / 32, BATCH);     // 24 x 32 x 8
    cvt_trans_kernel<<<gc, 256>>>(A);

    dim3 g1(36, 1, BATCH);                  // linearized upper triangle
    qk_exp_mma<<<g1, 256, SMEM_B>>>(mask);

    dim3 g2(DIM / 128, SEQ / 128, BATCH);   // 6 x 8 x 8
    pv_mma<<<g2, 256, PV_SMEM>>>(out);
}

// round 17
// speedup vs baseline: 1.0424x; 1.0424x over previous
#include <cuda_runtime.h>
#include <cstdint>

#define BATCH 8
#define SEQ   1024
#define DIM   768
#define EPS_F 1e-7f

// Both GEMMs: 128x128 block, 8 warps 64x32, BK=32, swizzled 32-word rows.
#define STAGES   3
#define STAGE_B  32768                      // A-op 16KB + B-op 16KB
#define SMEM_B   (STAGES * STAGE_B)         // 98304
#define PV_SMEM  (SMEM_B + 512)             // + den[128]
#define PADT 132                            // qk transpose-stage stride

// k-permutation within 8-groups: pos(k) = (k&3)*2 + (k>>2)
__device__ __forceinline__ int pcol(int c) {
    return (c & ~7) | (((c & 3) << 1) + ((c >> 2) & 1));
}

// Scratch (allocation-free rule: __device__ globals)
__device__ float g_Atf[(size_t)BATCH * SEQ * DIM];  // tf32, [S][D], D-permuted
__device__ float g_AT [(size_t)BATCH * DIM * SEQ];  // tf32, [D][S], S-permuted
__device__ float g_E[(size_t)BATCH * SEQ * SEQ];    // tf32 exp scores, col-permuted
__device__ float g_partial[(size_t)BATCH * SEQ * 32];

__device__ __forceinline__ uint32_t smem_u32(const void* p) {
    uint32_t a;
    asm("{ .reg .u64 t; cvta.to.shared.u64 t, %1; cvt.u32.u64 %0, t; }" : "=r"(a) : "l"(p));
    return a;
}
__device__ __forceinline__ uint32_t f2tf(float x) {
    uint32_t u; asm("cvt.rna.tf32.f32 %0, %1;" : "=r"(u) : "f"(x)); return u;
}
__device__ __forceinline__ float f2tff(float x) {
    return __uint_as_float(f2tf(x));
}
__device__ __forceinline__ void mma_tf32(float c[4],
                                         uint32_t a0, uint32_t a1, uint32_t a2, uint32_t a3,
                                         uint32_t b0, uint32_t b1) {
    asm("mma.sync.aligned.m16n8k8.row.col.f32.tf32.tf32.f32 "
        "{%0,%1,%2,%3}, {%4,%5,%6,%7}, {%8,%9}, {%0,%1,%2,%3};"
        : "+f"(c[0]), "+f"(c[1]), "+f"(c[2]), "+f"(c[3])
        : "r"(a0), "r"(a1), "r"(a2), "r"(a3), "r"(b0), "r"(b1));
}
__device__ __forceinline__ void cp16(uint32_t saddr, const void* g) {
    asm volatile("cp.async.cg.shared.global [%0], [%1], 16;" :: "r"(saddr), "l"(g));
}
#define CP_COMMIT() asm volatile("cp.async.commit_group;" ::: "memory")
#define CP_WAIT1()  asm volatile("cp.async.wait_group 1;" ::: "memory")

// swizzled fragment byte-offset inside a [rows][32 words] tile
#define SWOFF(row, ks) \
    ((uint32_t)(row) * 128u + (uint32_t)((((2*(ks)) + cb) ^ swz) << 4) + w8)

// ---------------------------------------------------------------------------
// Shared compute core with one-step fragment software pipelining (round-15).
// ---------------------------------------------------------------------------
#define COMPUTE_PIPE(AsBuf, BsBuf) do {                                       \
    uint2 bq[4], nbq[4];                                                      \
    _Pragma("unroll")                                                         \
    for (int nt = 0; nt < 4; nt++)                                            \
        bq[nt] = *(const uint2*)((BsBuf) + SWOFF(nBase + nt * 8 + qid, 0));   \
    _Pragma("unroll")                                                         \
    for (int ks = 0; ks < 4; ks++) {                                          \
        if (ks < 3) {                                                         \
            _Pragma("unroll")                                                 \
            for (int nt = 0; nt < 4; nt++)                                    \
                nbq[nt] = *(const uint2*)((BsBuf) +                           \
                    SWOFF(nBase + nt * 8 + qid, ks + 1));                     \
        }                                                                     \
        uint2 aL = *(const uint2*)((AsBuf) + SWOFF(mBase + qid, ks));         \
        uint2 aH = *(const uint2*)((AsBuf) + SWOFF(mBase + qid + 8, ks));     \
        _Pragma("unroll")                                                     \
        for (int mt = 0; mt < 4; mt++) {                                      \
            uint2 naL, naH;                                                   \
            if (mt < 3) {                                                     \
                naL = *(const uint2*)((AsBuf) +                               \
                    SWOFF(mBase + (mt + 1) * 16 + qid, ks));                  \
                naH = *(const uint2*)((AsBuf) +                               \
                    SWOFF(mBase + (mt + 1) * 16 + qid + 8, ks));              \
            }                                                                 \
            _Pragma("unroll")                                                 \
            for (int nt = 0; nt < 4; nt++)                                    \
                mma_tf32(acc[mt][nt], aL.x, aH.x, aL.y, aH.y,                 \
                         bq[nt].x, bq[nt].y);                                 \
            if (mt < 3) { aL = naL; aH = naH; }                               \
        }                                                                     \
        if (ks < 3) {                                                         \
            _Pragma("unroll")                                                 \
            for (int nt = 0; nt < 4; nt++) bq[nt] = nbq[nt];                  \
        }                                                                     \
    }                                                                         \
} while (0)

// ---------------------------------------------------------------------------
// Kernel 0: fused tf32 round + dual layout.
// Fb path: pure register permute, 2x LDG.128 -> 2x STG.128 (no SMEM).
// Tb path: SMEM 33-stride transpose with conflict-free scalar gathers/stores
// (round-15 proven form).
// ---------------------------------------------------------------------------
__global__ void __launch_bounds__(256) cvt_trans_kernel(const float* __restrict__ A)
{
    __shared__ float tile[32][33];
    const int b  = blockIdx.z;
    const int d0 = blockIdx.x * 32;
    const int s0 = blockIdx.y * 32;
    const int t  = threadIdx.x;
    const int tx = t & 31;
    const int ty = t >> 5;
    const float* Ab = A + (size_t)b * SEQ * DIM;

    // tile load for the transpose path
    #pragma unroll
    for (int j = 0; j < 4; j++)
        tile[ty + 8 * j][tx] = Ab[(size_t)(s0 + ty + 8 * j) * DIM + d0 + tx];

    // Fb stream: 128 threads, one 8-group each (32 rows x 4 groups)
    if (t < 128) {
        const int r   = t >> 2;
        const int grp = t & 3;
        const float* src = Ab + (size_t)(s0 + r) * DIM + d0 + grp * 8;
        float4 v = *(const float4*)src;
        float4 w = *(const float4*)(src + 4);
        // out positions [0..7] hold sources [0,4,1,5,2,6,3,7]
        float4 o0 = make_float4(f2tff(v.x), f2tff(w.x), f2tff(v.y), f2tff(w.y));
        float4 o1 = make_float4(f2tff(v.z), f2tff(w.z), f2tff(v.w), f2tff(w.w));
        float* dst = g_Atf + (size_t)b * SEQ * DIM
                   + (size_t)(s0 + r) * DIM + d0 + grp * 8;
        *(float4*)dst       = o0;
        *(float4*)(dst + 4) = o1;
    }
    __syncthreads();

    // Tb transpose: value at out pos tx = tile[invp(tx)][r]
    const int ivx = (tx & ~7) | ((tx >> 1) & 3) | ((tx & 1) << 2);   // invp
    float* Tb = g_AT + (size_t)b * DIM * SEQ;
    #pragma unroll
    for (int j = 0; j < 4; j++) {
        int r = ty + 8 * j;
        Tb[(size_t)(d0 + r) * SEQ + s0 + tx] = f2tff(tile[ivx][r]);
    }
}

// ---------------------------------------------------------------------------
// Kernel 1: E = exp(A A^T) * masks, triangle-linearized grid (36 tiles/batch).
// Mainloop order (PROVEN): wait_group 1 -> sync -> issue(it+2) -> compute(it).
// ---------------------------------------------------------------------------
__global__ void __launch_bounds__(256, 2) qk_exp_mma(const int* __restrict__ mask)
{
    extern __shared__ float dsm[];

    int by = 0, rem = blockIdx.x;
    while (rem >= 8 - by) { rem -= 8 - by; by++; }
    const int bx = by + rem;
    const bool offdiag = (bx > by);

    const int b       = blockIdx.z;
    const int rowBase = by * 128;
    const int colBase = bx * 128;
    const float* Ab = g_Atf + (size_t)b * SEQ * DIM;
    const int bS = b * SEQ;

    const int tid  = threadIdx.x;
    const int wid  = tid >> 5;
    const int lane = tid & 31;
    const int qid  = lane >> 2;
    const int tq   = lane & 3;
    const int mBase = (wid >> 2) * 64;
    const int nBase = (wid & 3) * 32;
    const int wr   = wid >> 2;
    const int wc   = wid & 3;

    const uint32_t cb  = (uint32_t)(tq >> 1);
    const uint32_t w8  = (uint32_t)((tq & 1) * 8);
    const uint32_t swz = (uint32_t)((qid & 3) << 1);

    const uint32_t sb = smem_u32(dsm);

    const float* gA[4]; const float* gB[4]; uint32_t dstT[4];
    #pragma unroll
    for (int l = 0; l < 4; l++) {
        int idx = tid + l * 256;
        int r   = idx >> 3;
        int c   = idx & 7;
        dstT[l] = (uint32_t)(r * 128 + ((c ^ ((r & 3) << 1)) << 4));
        gA[l]   = Ab + (size_t)(rowBase + r) * DIM + c * 4;
        gB[l]   = Ab + (size_t)(colBase + r) * DIM + c * 4;
    }

    float acc[4][4][4];
    #pragma unroll
    for (int i = 0; i < 4; i++)
        #pragma unroll
        for (int j = 0; j < 4; j++)
            #pragma unroll
            for (int k = 0; k < 4; k++) acc[i][j][k] = 0.f;

    const int NT = DIM / 32;   // 24

    #pragma unroll
    for (int s = 0; s < STAGES - 1; s++) {
        const uint32_t so = s * STAGE_B;
        const int k0 = s * 32;
        #pragma unroll
        for (int l = 0; l < 4; l++) {
            cp16(sb + so + dstT[l], gA[l] + k0);
            cp16(sb + so + 16384 + dstT[l], gB[l] + k0);
        }
        CP_COMMIT();
    }

    for (int it = 0; it < NT; it++) {
        CP_WAIT1();                 // per-thread: tile it complete
        __syncthreads();            // collective: stage(it) published, stage(it-1) free
        {
            const int tn = it + 2;
            if (tn < NT) {
                const uint32_t so = (tn % STAGES) * STAGE_B;
                const int k0 = tn * 32;
                #pragma unroll
                for (int l = 0; l < 4; l++) {
                    cp16(sb + so + dstT[l], gA[l] + k0);
                    cp16(sb + so + 16384 + dstT[l], gB[l] + k0);
                }
            }
            CP_COMMIT();
        }
        const char* As = (const char*)dsm + (it % STAGES) * STAGE_B;
        const char* Bs = As + 16384;
        COMPUTE_PIPE(As, Bs);
    }

    __syncthreads();
    float* stage = dsm;

    float cs[4][2];
    #pragma unroll
    for (int nt = 0; nt < 4; nt++) { cs[nt][0] = 0.f; cs[nt][1] = 0.f; }

    #pragma unroll
    for (int mt = 0; mt < 4; mt++) {
        const int rrl = mBase + mt * 16 + qid;
        const int rr  = rowBase + rrl;
        const int prr = pcol(rrl);
        const float mr0 = (float)mask[bS + rr];
        const float mr1 = (float)mask[bS + rr + 8];
        float s0 = 0.f, s1 = 0.f;
        #pragma unroll
        for (int nt = 0; nt < 4; nt++) {
            const int ccl = nBase + nt * 8 + tq * 2;
            const int cc  = colBase + ccl;
            const float mc0 = (float)mask[bS + cc];
            const float mc1 = (float)mask[bS + cc + 1];
            float e00 = f2tff(__expf(acc[mt][nt][0]) * mr0 * mc0);
            float e01 = f2tff(__expf(acc[mt][nt][1]) * mr0 * mc1);
            float e10 = f2tff(__expf(acc[mt][nt][2]) * mr1 * mc0);
            float e11 = f2tff(__expf(acc[mt][nt][3]) * mr1 * mc1);
            s0 += e00 + e01;
            s1 += e10 + e11;
            const int pc = colBase + pcol(ccl);
            float* er0 = &g_E[((size_t)bS + rr) * SEQ + pc];
            float* er1 = &g_E[((size_t)bS + rr + 8) * SEQ + pc];
            er0[0] = e00; er0[2] = e01;
            er1[0] = e10; er1[2] = e11;
            if (offdiag) {
                cs[nt][0] += e00 + e10;
                cs[nt][1] += e01 + e11;
                stage[ccl * PADT + prr]           = e00;
                stage[(ccl + 1) * PADT + prr]     = e01;
                stage[ccl * PADT + prr + 8]       = e10;
                stage[(ccl + 1) * PADT + prr + 8] = e11;
            }
        }
        s0 += __shfl_xor_sync(0xffffffffu, s0, 1);
        s0 += __shfl_xor_sync(0xffffffffu, s0, 2);
        s1 += __shfl_xor_sync(0xffffffffu, s1, 1);
        s1 += __shfl_xor_sync(0xffffffffu, s1, 2);
        if (tq == 0) {
            g_partial[((size_t)bS + rr) * 32 + bx * 4 + wc]     = s0;
            g_partial[((size_t)bS + rr + 8) * 32 + bx * 4 + wc] = s1;
        }
    }

    if (offdiag) {
        #pragma unroll
        for (int nt = 0; nt < 4; nt++) {
            #pragma unroll
            for (int h = 0; h < 2; h++) {
                float v = cs[nt][h];
                v += __shfl_xor_sync(0xffffffffu, v, 4);
                v += __shfl_xor_sync(0xffffffffu, v, 8);
                v += __shfl_xor_sync(0xffffffffu, v, 16);
                cs[nt][h] = v;
            }
        }
        if (qid == 0) {
            #pragma unroll
            for (int nt = 0; nt < 4; nt++) {
                const int cc = colBase + nBase + nt * 8 + tq * 2;
                g_partial[((size_t)bS + cc) * 32 + by * 4 + wr]         = cs[nt][0];
                g_partial[((size_t)bS + cc + 1) * 32 + by * 4 + wr]     = cs[nt][1];
                g_partial[((size_t)bS + cc) * 32 + by * 4 + 2 + wr]     = 0.f;
                g_partial[((size_t)bS + cc + 1) * 32 + by * 4 + 2 + wr] = 0.f;
            }
        }
        __syncthreads();
        #pragma unroll
        for (int l = 0; l < 16; l++) {
            int idx = tid + l * 256;
            int c   = idx >> 5;
            int r4  = (idx & 31) << 2;
            float4 v = *(float4*)&stage[c * PADT + r4];
            *(float4*)&g_E[((size_t)bS + colBase + c) * SEQ + rowBase + r4] = v;
        }
    }
}

// ---------------------------------------------------------------------------
// Kernel 2: out = (E @ A) / den.  Denominators folded into prologue (SMEM);
// mainloop order identical to the proven round-15 structure.
// ---------------------------------------------------------------------------
__global__ void __launch_bounds__(256, 2) pv_mma(float* __restrict__ out)
{
    extern __shared__ float dsm[];
    float* den_s = dsm + SMEM_B / 4;

    const int b       = blockIdx.z;
    const int rowBase = blockIdx.y * 128;
    const int colBase = blockIdx.x * 128;
    const float* ATb = g_AT + (size_t)b * DIM * SEQ;
    const float* Eb  = g_E  + (size_t)b * SEQ * SEQ;
    const int bS = b * SEQ;

    const int tid  = threadIdx.x;
    const int wid  = tid >> 5;
    const int lane = tid & 31;
    const int qid  = lane >> 2;
    const int tq   = lane & 3;
    const int mBase = (wid >> 2) * 64;
    const int nBase = (wid & 3) * 32;

    const uint32_t cb  = (uint32_t)(tq >> 1);
    const uint32_t w8  = (uint32_t)((tq & 1) * 8);
    const uint32_t swz = (uint32_t)((qid & 3) << 1);

    const uint32_t sb = smem_u32(dsm);

    const float* gE[4]; const float* gV[4]; uint32_t dstT[4];
    #pragma unroll
    for (int l = 0; l < 4; l++) {
        int idx = tid + l * 256;
        int r   = idx >> 3;
        int c   = idx & 7;
        dstT[l] = (uint32_t)(r * 128 + ((c ^ ((r & 3) << 1)) << 4));
        gE[l]   = Eb  + (size_t)(rowBase + r) * SEQ + c * 4;
        gV[l]   = ATb + (size_t)(colBase + r) * SEQ + c * 4;
    }

    #pragma unroll
    for (int s = 0; s < STAGES - 1; s++) {
        const uint32_t so = s * STAGE_B;
        const int k0 = s * 32;
        #pragma unroll
        for (int l = 0; l < 4; l++) {
            cp16(sb + so + dstT[l], gE[l] + k0);
            cp16(sb + so + 16384 + dstT[l], gV[l] + k0);
        }
        CP_COMMIT();
    }

    // denominator fold: 2 threads/row; published by first mainloop sync
    {
        const int row = tid >> 1;
        const int h   = tid & 1;
        const float* p = g_partial + ((size_t)bS + rowBase + row) * 32 + h * 16;
        float s = 0.f;
        #pragma unroll
        for (int j = 0; j < 16; j++) s += p[j];
        s += __shfl_xor_sync(0xffffffffu, s, 1);
        if (h == 0) den_s[row] = s + EPS_F;
    }

    float acc[4][4][4];
    #pragma unroll
    for (int i = 0; i < 4; i++)
        #pragma unroll
        for (int j = 0; j < 4; j++)
            #pragma unroll
            for (int k = 0; k < 4; k++) acc[i][j][k] = 0.f;

    const int NT = SEQ / 32;   // 32

    for (int it = 0; it < NT; it++) {
        CP_WAIT1();
        __syncthreads();
        {
            const int tn = it + 2;
            if (tn < NT) {
                const uint32_t so = (tn % STAGES) * STAGE_B;
                const int k0 = tn * 32;
                #pragma unroll
                for (int l = 0; l < 4; l++) {
                    cp16(sb + so + dstT[l], gE[l] + k0);
                    cp16(sb + so + 16384 + dstT[l], gV[l] + k0);
                }
            }
            CP_COMMIT();
        }
        const char* Es = (const char*)dsm + (it % STAGES) * STAGE_B;
        const char* Vs = Es + 16384;
        COMPUTE_PIPE(Es, Vs);
    }

    // Epilogue: scale by 1/den (from SMEM), coalesced float2 stores.
    #pragma unroll
    for (int mt = 0; mt < 4; mt++) {
        const int rl = mBase + mt * 16 + qid;
        const int rr = rowBase + rl;
        const float inv0 = 1.0f / den_s[rl];
        const float inv1 = 1.0f / den_s[rl + 8];
        #pragma unroll
        for (int nt = 0; nt < 4; nt++) {
            const int cc = colBase + nBase + nt * 8 + tq * 2;
            *(float2*)&out[((size_t)bS + rr) * DIM + cc] =
                make_float2(acc[mt][nt][0] * inv0, acc[mt][nt][1] * inv0);
            *(float2*)&out[((size_t)bS + rr + 8) * DIM + cc] =
                make_float2(acc[mt][nt][2] * inv1, acc[mt][nt][3] * inv1);
        }
    }
}

// ---------------------------------------------------------------------------
extern "C" void kernel_launch(void* const* d_in, const int* in_sizes, int n_in,
                              void* d_out, int out_size)
{
    const float* A    = (const float*)d_in[0];
    const int*   mask = (const int*)d_in[1];
    float*       out  = (float*)d_out;

    cudaFuncSetAttribute(qk_exp_mma, cudaFuncAttributeMaxDynamicSharedMemorySize, SMEM_B);
    cudaFuncSetAttribute(pv_mma,     cudaFuncAttributeMaxDynamicSharedMemorySize, PV_SMEM);

    dim3 gc(DIM / 32, SEQ / 32, BATCH);     // 24 x 32 x 8
    cvt_trans_kernel<<<gc, 256>>>(A);

    dim3 g1(36, 1, BATCH);                  // linearized upper triangle
    qk_exp_mma<<<g1, 256, SMEM_B>>>(mask);

    dim3 g2(DIM / 128, SEQ / 128, BATCH);   // 6 x 8 x 8
    pv_mma<<<g2, 256, PV_SMEM>>>(out);
}